// round 1
// baseline (speedup 1.0000x reference)
#include <cuda_runtime.h>
#include <cuda_bf16.h>
#include <math.h>

#define B_ 2
#define S_ 2048
#define E_ 1024
#define H_ 16
#define D_ 64
#define M_ (B_*S_)   // 4096 rows

// ---- scratch (static device globals; no allocation APIs allowed) ----
__device__ float g_Q [M_*E_];
__device__ float g_Kb[M_*E_];
__device__ float g_Vb[M_*E_];
__device__ float g_AO[M_*E_];
__device__ float g_X1[M_*E_];
__device__ float g_T [M_*E_];
__device__ float g_HM[M_*E_];

// ============================================================================
// SGEMM: C[M,N] = A[M,K] @ B[K,N] (+bias). 128x128x16 tile, 8x8 per thread.
// ============================================================================
__global__ __launch_bounds__(256) void sgemm_kernel(
    const float* __restrict__ A, const float* __restrict__ Bm,
    const float* __restrict__ bias, float* __restrict__ C,
    int M, int N, int K)
{
    constexpr int BK = 16;
    __shared__ float As[BK][128];
    __shared__ float Bs[BK][128];
    const int tid = threadIdx.x;
    const int bx = blockIdx.x, by = blockIdx.y;
    const int tx = tid & 15, ty = tid >> 4;
    const float* Ag = A + (size_t)by * 128 * K;
    const float* Bg = Bm + bx * 128;

    float acc[8][8];
    #pragma unroll
    for (int i = 0; i < 8; i++)
        #pragma unroll
        for (int j = 0; j < 8; j++) acc[i][j] = 0.f;

    for (int k0 = 0; k0 < K; k0 += BK) {
        // A tile 128x16 -> transposed into As[k][m]
        #pragma unroll
        for (int i = 0; i < 2; i++) {
            int pos = tid + i * 256;        // 512 float4 slots
            int row = pos >> 2;
            int c4  = (pos & 3) << 2;
            float4 v = *reinterpret_cast<const float4*>(Ag + (size_t)row * K + k0 + c4);
            As[c4 + 0][row] = v.x;
            As[c4 + 1][row] = v.y;
            As[c4 + 2][row] = v.z;
            As[c4 + 3][row] = v.w;
        }
        // B tile 16x128
        #pragma unroll
        for (int i = 0; i < 2; i++) {
            int pos = tid + i * 256;
            int row = pos >> 5;
            int c4  = (pos & 31) << 2;
            *reinterpret_cast<float4*>(&Bs[row][c4]) =
                *reinterpret_cast<const float4*>(Bg + (size_t)(k0 + row) * N + c4);
        }
        __syncthreads();
        #pragma unroll
        for (int kk = 0; kk < BK; kk++) {
            float4 a0 = *reinterpret_cast<const float4*>(&As[kk][ty * 8]);
            float4 a1 = *reinterpret_cast<const float4*>(&As[kk][ty * 8 + 4]);
            float4 b0 = *reinterpret_cast<const float4*>(&Bs[kk][tx * 8]);
            float4 b1 = *reinterpret_cast<const float4*>(&Bs[kk][tx * 8 + 4]);
            float ra[8] = {a0.x, a0.y, a0.z, a0.w, a1.x, a1.y, a1.z, a1.w};
            float rb[8] = {b0.x, b0.y, b0.z, b0.w, b1.x, b1.y, b1.z, b1.w};
            #pragma unroll
            for (int i = 0; i < 8; i++)
                #pragma unroll
                for (int j = 0; j < 8; j++)
                    acc[i][j] += ra[i] * rb[j];
        }
        __syncthreads();
    }

    #pragma unroll
    for (int i = 0; i < 8; i++) {
        size_t row = (size_t)by * 128 + ty * 8 + i;
        #pragma unroll
        for (int j = 0; j < 8; j += 4) {
            int col = bx * 128 + tx * 8 + j;
            float4 v;
            v.x = acc[i][j]; v.y = acc[i][j+1]; v.z = acc[i][j+2]; v.w = acc[i][j+3];
            if (bias) {
                v.x += bias[col]; v.y += bias[col+1]; v.z += bias[col+2]; v.w += bias[col+3];
            }
            *reinterpret_cast<float4*>(C + row * N + col) = v;
        }
    }
}

// ============================================================================
// Flash-style fp32 attention + quantum cumprod mix, fused head-transpose out.
// Tq=64 query rows per block, Tk=32 key rows per iteration, 256 threads.
// Thread (ty,tx): 4 q-rows (ty*4+i), 2 k-cols (tx*2+j), 4 out-dims (tx*4+j).
// ============================================================================
__global__ __launch_bounds__(256) void attn_kernel(
    const float* __restrict__ Q, const float* __restrict__ K,
    const float* __restrict__ V, const int* __restrict__ mask,
    const float* __restrict__ qwp, float* __restrict__ AO)
{
    const int bh = blockIdx.y;
    const int b  = bh >> 4;
    const int h  = bh & 15;
    const int qt = blockIdx.x;
    const int tid = threadIdx.x;
    const int tx = tid & 15, ty = tid >> 4;

    __shared__ float Qs[64][65];
    __shared__ float Ks[32][65];
    __shared__ float Vs[32][68];   // stride 68 -> 16B aligned rows for float4
    __shared__ float Ps[64][33];
    __shared__ int   msk[32];

    // load Q tile (raw q, unscaled — also used for quantum cumprod)
    {
        const float* Qg = Q + ((size_t)(b * S_ + qt * 64)) * E_ + h * 64;
        #pragma unroll
        for (int i = 0; i < 4; i++) {
            int pos = tid + i * 256;     // 1024 float4 slots
            int row = pos >> 4;
            int c4  = (pos & 15) << 2;
            float4 v = *reinterpret_cast<const float4*>(Qg + (size_t)row * E_ + c4);
            Qs[row][c4+0] = v.x; Qs[row][c4+1] = v.y;
            Qs[row][c4+2] = v.z; Qs[row][c4+3] = v.w;
        }
    }

    float m[4], l[4], O[4][4];
    #pragma unroll
    for (int i = 0; i < 4; i++) {
        m[i] = -INFINITY; l[i] = 0.f;
        #pragma unroll
        for (int j = 0; j < 4; j++) O[i][j] = 0.f;
    }

    const float* Kg = K + ((size_t)(b * S_)) * E_ + h * 64;
    const float* Vg = V + ((size_t)(b * S_)) * E_ + h * 64;

    for (int kt = 0; kt < S_ / 32; kt++) {
        __syncthreads();   // previous PV done before overwriting K/V tiles
        #pragma unroll
        for (int i = 0; i < 2; i++) {
            int pos = tid + i * 256;     // 512 float4 slots per tile
            int row = pos >> 4;
            int c4  = (pos & 15) << 2;
            float4 kv = *reinterpret_cast<const float4*>(Kg + (size_t)(kt*32 + row) * E_ + c4);
            Ks[row][c4+0] = kv.x; Ks[row][c4+1] = kv.y;
            Ks[row][c4+2] = kv.z; Ks[row][c4+3] = kv.w;
            float4 vv = *reinterpret_cast<const float4*>(Vg + (size_t)(kt*32 + row) * E_ + c4);
            *reinterpret_cast<float4*>(&Vs[row][c4]) = vv;
        }
        if (tid < 32) msk[tid] = mask[b * S_ + kt * 32 + tid];
        __syncthreads();

        // S = (Q @ K^T) * 0.125, masked
        float Sv[4][2];
        #pragma unroll
        for (int i = 0; i < 4; i++) { Sv[i][0] = 0.f; Sv[i][1] = 0.f; }
        #pragma unroll 8
        for (int d = 0; d < 64; d++) {
            float kv0 = Ks[tx*2 + 0][d];
            float kv1 = Ks[tx*2 + 1][d];
            #pragma unroll
            for (int i = 0; i < 4; i++) {
                float qv = Qs[ty*4 + i][d];
                Sv[i][0] += qv * kv0;
                Sv[i][1] += qv * kv1;
            }
        }
        bool valid0 = msk[tx*2 + 0] != 0;
        bool valid1 = msk[tx*2 + 1] != 0;
        #pragma unroll
        for (int i = 0; i < 4; i++) {
            Sv[i][0] = valid0 ? Sv[i][0] * 0.125f : -INFINITY;
            Sv[i][1] = valid1 ? Sv[i][1] * 0.125f : -INFINITY;
        }

        // online softmax per row (16 lanes share a row; xor<16 stays in half-warp)
        #pragma unroll
        for (int i = 0; i < 4; i++) {
            float tm = fmaxf(Sv[i][0], Sv[i][1]);
            #pragma unroll
            for (int off = 1; off < 16; off <<= 1)
                tm = fmaxf(tm, __shfl_xor_sync(0xffffffffu, tm, off));
            float mn = fmaxf(m[i], tm);
            float p0 = expf(Sv[i][0] - mn);
            float p1 = expf(Sv[i][1] - mn);
            float ts = p0 + p1;
            #pragma unroll
            for (int off = 1; off < 16; off <<= 1)
                ts += __shfl_xor_sync(0xffffffffu, ts, off);
            float corr = expf(m[i] - mn);
            l[i] = l[i] * corr + ts;
            m[i] = mn;
            #pragma unroll
            for (int j = 0; j < 4; j++) O[i][j] *= corr;
            Ps[ty*4 + i][tx*2 + 0] = p0;
            Ps[ty*4 + i][tx*2 + 1] = p1;
        }
        __syncthreads();

        // O += P @ V
        #pragma unroll 4
        for (int c = 0; c < 32; c++) {
            float4 vv = *reinterpret_cast<const float4*>(&Vs[c][tx*4]);
            #pragma unroll
            for (int i = 0; i < 4; i++) {
                float pv = Ps[ty*4 + i][c];
                O[i][0] += pv * vv.x; O[i][1] += pv * vv.y;
                O[i][2] += pv * vv.z; O[i][3] += pv * vv.w;
            }
        }
    }
    __syncthreads();

    // quantum = cumprod(cos(q_row)) — overwrite Qs in place (1 thread per row)
    if (tid < 64) {
        float p = 1.f;
        #pragma unroll 8
        for (int d = 0; d < 64; d++) { p *= cosf(Qs[tid][d]); Qs[tid][d] = p; }
    }
    __syncthreads();

    const float w = 1.f / (1.f + expf(-qwp[0]));
    float* AOg = AO + ((size_t)(b * S_ + qt * 64)) * E_ + h * 64;
    #pragma unroll
    for (int i = 0; i < 4; i++) {
        int r = ty * 4 + i;
        float invl = 1.f / l[i];
        int d0 = tx * 4;
        float4 o;
        o.x = w * Qs[r][d0+0] + (1.f - w) * O[i][0] * invl;
        o.y = w * Qs[r][d0+1] + (1.f - w) * O[i][1] * invl;
        o.z = w * Qs[r][d0+2] + (1.f - w) * O[i][2] * invl;
        o.w = w * Qs[r][d0+3] + (1.f - w) * O[i][3] * invl;
        *reinterpret_cast<float4*>(AOg + (size_t)r * E_ + d0) = o;
    }
}

// ============================================================================
// out = LayerNorm(X + Y) * g + b     (one block per row of 1024)
// ============================================================================
__global__ __launch_bounds__(256) void add_ln_kernel(
    const float* __restrict__ X, const float* __restrict__ Y,
    const float* __restrict__ g, const float* __restrict__ bt,
    float* __restrict__ out)
{
    const int row = blockIdx.x;
    const int tid = threadIdx.x;
    __shared__ float buf[1024];
    __shared__ float red[8];

    const float* Xr = X + (size_t)row * 1024;
    const float* Yr = Y + (size_t)row * 1024;

    float s = 0.f;
    #pragma unroll
    for (int i = 0; i < 4; i++) {
        int idx = tid + i * 256;
        float v = Xr[idx] + Yr[idx];
        buf[idx] = v;
        s += v;
    }
    #pragma unroll
    for (int off = 16; off; off >>= 1) s += __shfl_xor_sync(~0u, s, off);
    if ((tid & 31) == 0) red[tid >> 5] = s;
    __syncthreads();
    float tot = 0.f;
    #pragma unroll
    for (int i = 0; i < 8; i++) tot += red[i];
    const float mean = tot * (1.f / 1024.f);
    __syncthreads();

    float vs = 0.f;
    #pragma unroll
    for (int i = 0; i < 4; i++) {
        float d = buf[tid + i * 256] - mean;
        vs += d * d;
    }
    #pragma unroll
    for (int off = 16; off; off >>= 1) vs += __shfl_xor_sync(~0u, vs, off);
    if ((tid & 31) == 0) red[tid >> 5] = vs;
    __syncthreads();
    float vtot = 0.f;
    #pragma unroll
    for (int i = 0; i < 8; i++) vtot += red[i];
    const float rstd = rsqrtf(vtot * (1.f / 1024.f) + 1e-5f);

    #pragma unroll
    for (int i = 0; i < 4; i++) {
        int idx = tid + i * 256;
        out[(size_t)row * 1024 + idx] = (buf[idx] - mean) * rstd * g[idx] + bt[idx];
    }
}

// ============================================================================
// HM = wgt*cumprod(cos(X1_row)) + (1-wgt)*relu(H1)   (one block per row)
// Parallel inclusive product scan: 4 elems/thread + 256-thread Hillis-Steele.
// ============================================================================
__global__ __launch_bounds__(256) void ffn_mix_kernel(
    const float* __restrict__ X1, const float* __restrict__ H1,
    const float* __restrict__ qwp, float* __restrict__ HM)
{
    const int row = blockIdx.x;
    const int tid = threadIdx.x;
    __shared__ float seg[256];

    float4 xv = *reinterpret_cast<const float4*>(X1 + (size_t)row * 1024 + tid * 4);
    float c0 = cosf(xv.x), c1 = cosf(xv.y), c2 = cosf(xv.z), c3 = cosf(xv.w);
    float p = c0 * c1 * c2 * c3;
    seg[tid] = p;
    __syncthreads();
    #pragma unroll
    for (int off = 1; off < 256; off <<= 1) {
        float t = (tid >= off) ? seg[tid - off] : 1.f;
        __syncthreads();
        seg[tid] *= t;
        __syncthreads();
    }
    float pre = (tid > 0) ? seg[tid - 1] : 1.f;
    float q0 = pre * c0;
    float q1 = q0 * c1;
    float q2 = q1 * c2;
    float q3 = q2 * c3;

    const float w = 1.f / (1.f + expf(-qwp[0]));
    float4 hv = *reinterpret_cast<const float4*>(H1 + (size_t)row * 1024 + tid * 4);
    float4 o;
    o.x = w * q0 + (1.f - w) * fmaxf(hv.x, 0.f);
    o.y = w * q1 + (1.f - w) * fmaxf(hv.y, 0.f);
    o.z = w * q2 + (1.f - w) * fmaxf(hv.z, 0.f);
    o.w = w * q3 + (1.f - w) * fmaxf(hv.w, 0.f);
    *reinterpret_cast<float4*>(HM + (size_t)row * 1024 + tid * 4) = o;
}

// ============================================================================
// launch
// ============================================================================
extern "C" void kernel_launch(void* const* d_in, const int* in_sizes, int n_in,
                              void* d_out, int out_size)
{
    const float* x       = (const float*)d_in[0];
    const int*   mask    = (const int*)  d_in[1];
    const float* wq      = (const float*)d_in[2];
    const float* wk      = (const float*)d_in[3];
    const float* wv      = (const float*)d_in[4];
    const float* wo      = (const float*)d_in[5];
    const float* attn_qw = (const float*)d_in[7];
    const float* w1      = (const float*)d_in[8];
    const float* b1      = (const float*)d_in[9];
    const float* w2      = (const float*)d_in[10];
    const float* b2      = (const float*)d_in[11];
    const float* ffn_qw  = (const float*)d_in[13];
    const float* ln1g    = (const float*)d_in[14];
    const float* ln1b    = (const float*)d_in[15];
    const float* ln2g    = (const float*)d_in[16];
    const float* ln2b    = (const float*)d_in[17];
    float* out = (float*)d_out;

    float *Qp, *Kp, *Vp, *AOp, *X1p, *Tp, *HMp;
    cudaGetSymbolAddress((void**)&Qp,  g_Q);
    cudaGetSymbolAddress((void**)&Kp,  g_Kb);
    cudaGetSymbolAddress((void**)&Vp,  g_Vb);
    cudaGetSymbolAddress((void**)&AOp, g_AO);
    cudaGetSymbolAddress((void**)&X1p, g_X1);
    cudaGetSymbolAddress((void**)&Tp,  g_T);
    cudaGetSymbolAddress((void**)&HMp, g_HM);

    dim3 gg(E_ / 128, M_ / 128);   // (8, 32)

    // QKV projections
    sgemm_kernel<<<gg, 256>>>(x, wq, nullptr, Qp, M_, E_, E_);
    sgemm_kernel<<<gg, 256>>>(x, wk, nullptr, Kp, M_, E_, E_);
    sgemm_kernel<<<gg, 256>>>(x, wv, nullptr, Vp, M_, E_, E_);

    // attention + quantum mix (outputs [b,s,e] layout directly)
    attn_kernel<<<dim3(S_ / 64, B_ * H_), 256>>>(Qp, Kp, Vp, mask, attn_qw, AOp);

    // output projection, residual + LN1
    sgemm_kernel<<<gg, 256>>>(AOp, wo, nullptr, Tp, M_, E_, E_);
    add_ln_kernel<<<M_, 256>>>(x, Tp, ln1g, ln1b, X1p);

    // FFN: H1 = x1@w1 + b1 ; mix with cumprod(cos(x1)) ; @w2 + b2 ; LN2
    sgemm_kernel<<<gg, 256>>>(X1p, w1, b1, Tp, M_, E_, E_);
    ffn_mix_kernel<<<M_, 256>>>(X1p, Tp, ffn_qw, HMp);
    sgemm_kernel<<<gg, 256>>>(HMp, w2, b2, Tp, M_, E_, E_);
    add_ln_kernel<<<M_, 256>>>(X1p, Tp, ln2g, ln2b, out);
}

// round 4
// speedup vs baseline: 1.4724x; 1.4724x over previous
#include <cuda_runtime.h>
#include <cuda_bf16.h>
#include <stdint.h>
#include <math.h>

#define B_ 2
#define S_ 2048
#define E_ 1024
#define H_ 16
#define D_ 64
#define M_ (B_*S_)   // 4096 rows

// ---- scratch (static device globals; no allocation APIs allowed) ----
__device__ float g_Q [M_*E_];
__device__ float g_Kb[M_*E_];
__device__ float g_Vb[M_*E_];
__device__ float g_AO[M_*E_];
__device__ float g_X1[M_*E_];
__device__ float g_T [M_*E_];
__device__ float g_HM[M_*E_];

// ============================================================================
// bf16x3 split-precision tensor-core GEMM.
// C[M,N] = A[M,K] @ B[K,N] (+bias), fp32 in/out, ~1e-5 rel accuracy.
// A = A_hi + A_lo (bf16 each); C ≈ Ah*Bh + Ah*Bl + Al*Bh.
// Tile 128x128x32, 256 threads, 8 warps (2 M x 4 N), warp tile 64x32,
// mma.sync.m16n8k16 bf16 with fp32 accumulators.
// ============================================================================

__device__ __forceinline__ uint32_t smem_u32(const void* p) {
    return (uint32_t)__cvta_generic_to_shared(p);
}

__device__ __forceinline__ void ldsm_x4(uint32_t r[4], uint32_t addr) {
    asm volatile("ldmatrix.sync.aligned.m8n8.x4.shared.b16 {%0,%1,%2,%3}, [%4];"
                 : "=r"(r[0]), "=r"(r[1]), "=r"(r[2]), "=r"(r[3]) : "r"(addr));
}
__device__ __forceinline__ void ldsm_x4_t(uint32_t r[4], uint32_t addr) {
    asm volatile("ldmatrix.sync.aligned.m8n8.x4.trans.shared.b16 {%0,%1,%2,%3}, [%4];"
                 : "=r"(r[0]), "=r"(r[1]), "=r"(r[2]), "=r"(r[3]) : "r"(addr));
}
__device__ __forceinline__ void mma_bf16(float c[4], const uint32_t a[4], const uint32_t b[2]) {
    asm volatile(
        "mma.sync.aligned.m16n8k16.row.col.f32.bf16.bf16.f32 "
        "{%0,%1,%2,%3}, {%4,%5,%6,%7}, {%8,%9}, {%0,%1,%2,%3};"
        : "+f"(c[0]), "+f"(c[1]), "+f"(c[2]), "+f"(c[3])
        : "r"(a[0]), "r"(a[1]), "r"(a[2]), "r"(a[3]), "r"(b[0]), "r"(b[1]));
}

__global__ __launch_bounds__(256) void gemm_tc_kernel(
    const float* __restrict__ A, const float* __restrict__ Bm,
    const float* __restrict__ bias, float* __restrict__ C,
    int M, int N, int K)
{
    // smem hi/lo planes. A tile 128x32 (+8 pad): [128][40].
    // B tile 32x128 (+8 pad): [32][136].
    __shared__ __nv_bfloat16 As[2][128][40];
    __shared__ __nv_bfloat16 Bs[2][32][136];

    const int tid  = threadIdx.x;
    const int lane = tid & 31;
    const int wid  = tid >> 5;
    const int warp_m = wid >> 2;       // 0..1
    const int warp_n = wid & 3;        // 0..3
    const int bx = blockIdx.x, by = blockIdx.y;

    const float* Ag = A + (size_t)(by * 128) * K;
    const float* Bg = Bm + (size_t)bx * 128;

    float acc[4][4][4];
    #pragma unroll
    for (int i = 0; i < 4; i++)
        #pragma unroll
        for (int j = 0; j < 4; j++)
            #pragma unroll
            for (int e = 0; e < 4; e++) acc[i][j][e] = 0.f;

    // ldmatrix lane addressing
    const int arow = lane & 15;
    const int acol = (lane >> 4) << 3;                    // 0 or 8
    const int brow = (lane & 7) + (lane & 8);             // 0..15
    const int bcol = (lane & 16) >> 1;                    // 0 or 8

    const uint32_t as_hi = smem_u32(&As[0][0][0]);
    const uint32_t as_lo = smem_u32(&As[1][0][0]);
    const uint32_t bs_hi = smem_u32(&Bs[0][0][0]);
    const uint32_t bs_lo = smem_u32(&Bs[1][0][0]);

    for (int k0 = 0; k0 < K; k0 += 32) {
        __syncthreads();
        // ---- load + split A tile 128x32 ----
        #pragma unroll
        for (int i = 0; i < 4; i++) {
            int pos = tid + i * 256;           // 1024 float4 slots
            int m  = pos >> 3;
            int kq = (pos & 7) << 2;
            float4 v = *reinterpret_cast<const float4*>(Ag + (size_t)m * K + k0 + kq);
            __nv_bfloat16 h0 = __float2bfloat16_rn(v.x);
            __nv_bfloat16 h1 = __float2bfloat16_rn(v.y);
            __nv_bfloat16 h2 = __float2bfloat16_rn(v.z);
            __nv_bfloat16 h3 = __float2bfloat16_rn(v.w);
            __nv_bfloat16 l0 = __float2bfloat16_rn(v.x - __bfloat162float(h0));
            __nv_bfloat16 l1 = __float2bfloat16_rn(v.y - __bfloat162float(h1));
            __nv_bfloat16 l2 = __float2bfloat16_rn(v.z - __bfloat162float(h2));
            __nv_bfloat16 l3 = __float2bfloat16_rn(v.w - __bfloat162float(h3));
            *reinterpret_cast<__nv_bfloat162*>(&As[0][m][kq + 0]) = __nv_bfloat162(h0, h1);
            *reinterpret_cast<__nv_bfloat162*>(&As[0][m][kq + 2]) = __nv_bfloat162(h2, h3);
            *reinterpret_cast<__nv_bfloat162*>(&As[1][m][kq + 0]) = __nv_bfloat162(l0, l1);
            *reinterpret_cast<__nv_bfloat162*>(&As[1][m][kq + 2]) = __nv_bfloat162(l2, l3);
        }
        // ---- load + split B tile 32x128 ----
        #pragma unroll
        for (int i = 0; i < 4; i++) {
            int pos = tid + i * 256;
            int kk = pos >> 5;
            int nq = (pos & 31) << 2;
            float4 v = *reinterpret_cast<const float4*>(Bg + (size_t)(k0 + kk) * N + nq);
            __nv_bfloat16 h0 = __float2bfloat16_rn(v.x);
            __nv_bfloat16 h1 = __float2bfloat16_rn(v.y);
            __nv_bfloat16 h2 = __float2bfloat16_rn(v.z);
            __nv_bfloat16 h3 = __float2bfloat16_rn(v.w);
            __nv_bfloat16 l0 = __float2bfloat16_rn(v.x - __bfloat162float(h0));
            __nv_bfloat16 l1 = __float2bfloat16_rn(v.y - __bfloat162float(h1));
            __nv_bfloat16 l2 = __float2bfloat16_rn(v.z - __bfloat162float(h2));
            __nv_bfloat16 l3 = __float2bfloat16_rn(v.w - __bfloat162float(h3));
            *reinterpret_cast<__nv_bfloat162*>(&Bs[0][kk][nq + 0]) = __nv_bfloat162(h0, h1);
            *reinterpret_cast<__nv_bfloat162*>(&Bs[0][kk][nq + 2]) = __nv_bfloat162(h2, h3);
            *reinterpret_cast<__nv_bfloat162*>(&Bs[1][kk][nq + 0]) = __nv_bfloat162(l0, l1);
            *reinterpret_cast<__nv_bfloat162*>(&Bs[1][kk][nq + 2]) = __nv_bfloat162(l2, l3);
        }
        __syncthreads();

        #pragma unroll
        for (int ks = 0; ks < 2; ks++) {
            const int kb = ks * 16;
            uint32_t ah[4][4], al[4][4], bh[4][2], bl[4][2];
            #pragma unroll
            for (int mt = 0; mt < 4; mt++) {
                uint32_t off = ((uint32_t)(warp_m * 64 + mt * 16 + arow) * 40 + kb + acol) * 2;
                ldsm_x4(ah[mt], as_hi + off);
                ldsm_x4(al[mt], as_lo + off);
            }
            #pragma unroll
            for (int np = 0; np < 2; np++) {
                uint32_t off = ((uint32_t)(kb + brow) * 136 + warp_n * 32 + np * 16 + bcol) * 2;
                uint32_t r[4];
                ldsm_x4_t(r, bs_hi + off);
                bh[np*2][0] = r[0]; bh[np*2][1] = r[1];
                bh[np*2+1][0] = r[2]; bh[np*2+1][1] = r[3];
                ldsm_x4_t(r, bs_lo + off);
                bl[np*2][0] = r[0]; bl[np*2][1] = r[1];
                bl[np*2+1][0] = r[2]; bl[np*2+1][1] = r[3];
            }
            #pragma unroll
            for (int mt = 0; mt < 4; mt++)
                #pragma unroll
                for (int nt = 0; nt < 4; nt++) {
                    mma_bf16(acc[mt][nt], ah[mt], bh[nt]);
                    mma_bf16(acc[mt][nt], ah[mt], bl[nt]);
                    mma_bf16(acc[mt][nt], al[mt], bh[nt]);
                }
        }
    }

    // ---- epilogue ----
    const int row0 = by * 128 + warp_m * 64 + (lane >> 2);
    const int col0 = bx * 128 + warp_n * 32 + ((lane & 3) << 1);
    #pragma unroll
    for (int mt = 0; mt < 4; mt++) {
        #pragma unroll
        for (int nt = 0; nt < 4; nt++) {
            int r = row0 + mt * 16;
            int c = col0 + nt * 8;
            float bb0 = 0.f, bb1 = 0.f;
            if (bias) { bb0 = bias[c]; bb1 = bias[c + 1]; }
            float2 v0 = make_float2(acc[mt][nt][0] + bb0, acc[mt][nt][1] + bb1);
            float2 v1 = make_float2(acc[mt][nt][2] + bb0, acc[mt][nt][3] + bb1);
            *reinterpret_cast<float2*>(C + (size_t)r * N + c) = v0;
            *reinterpret_cast<float2*>(C + (size_t)(r + 8) * N + c) = v1;
        }
    }
}

// ============================================================================
// Flash-style fp32 attention + quantum cumprod mix, fused head-transpose out.
// ============================================================================
__global__ __launch_bounds__(256) void attn_kernel(
    const float* __restrict__ Q, const float* __restrict__ K,
    const float* __restrict__ V, const int* __restrict__ mask,
    const float* __restrict__ qwp, float* __restrict__ AO)
{
    const int bh = blockIdx.y;
    const int b  = bh >> 4;
    const int h  = bh & 15;
    const int qt = blockIdx.x;
    const int tid = threadIdx.x;
    const int tx = tid & 15, ty = tid >> 4;

    __shared__ float Qs[64][65];
    __shared__ float Ks[32][65];
    __shared__ float Vs[32][68];
    __shared__ float Ps[64][33];
    __shared__ int   msk[32];

    {
        const float* Qg = Q + ((size_t)(b * S_ + qt * 64)) * E_ + h * 64;
        #pragma unroll
        for (int i = 0; i < 4; i++) {
            int pos = tid + i * 256;
            int row = pos >> 4;
            int c4  = (pos & 15) << 2;
            float4 v = *reinterpret_cast<const float4*>(Qg + (size_t)row * E_ + c4);
            Qs[row][c4+0] = v.x; Qs[row][c4+1] = v.y;
            Qs[row][c4+2] = v.z; Qs[row][c4+3] = v.w;
        }
    }

    float m[4], l[4], O[4][4];
    #pragma unroll
    for (int i = 0; i < 4; i++) {
        m[i] = -INFINITY; l[i] = 0.f;
        #pragma unroll
        for (int j = 0; j < 4; j++) O[i][j] = 0.f;
    }

    const float* Kg = K + ((size_t)(b * S_)) * E_ + h * 64;
    const float* Vg = V + ((size_t)(b * S_)) * E_ + h * 64;

    for (int kt = 0; kt < S_ / 32; kt++) {
        __syncthreads();
        #pragma unroll
        for (int i = 0; i < 2; i++) {
            int pos = tid + i * 256;
            int row = pos >> 4;
            int c4  = (pos & 15) << 2;
            float4 kv = *reinterpret_cast<const float4*>(Kg + (size_t)(kt*32 + row) * E_ + c4);
            Ks[row][c4+0] = kv.x; Ks[row][c4+1] = kv.y;
            Ks[row][c4+2] = kv.z; Ks[row][c4+3] = kv.w;
            float4 vv = *reinterpret_cast<const float4*>(Vg + (size_t)(kt*32 + row) * E_ + c4);
            *reinterpret_cast<float4*>(&Vs[row][c4]) = vv;
        }
        if (tid < 32) msk[tid] = mask[b * S_ + kt * 32 + tid];
        __syncthreads();

        float Sv[4][2];
        #pragma unroll
        for (int i = 0; i < 4; i++) { Sv[i][0] = 0.f; Sv[i][1] = 0.f; }
        #pragma unroll 8
        for (int d = 0; d < 64; d++) {
            float kv0 = Ks[tx*2 + 0][d];
            float kv1 = Ks[tx*2 + 1][d];
            #pragma unroll
            for (int i = 0; i < 4; i++) {
                float qv = Qs[ty*4 + i][d];
                Sv[i][0] += qv * kv0;
                Sv[i][1] += qv * kv1;
            }
        }
        bool valid0 = msk[tx*2 + 0] != 0;
        bool valid1 = msk[tx*2 + 1] != 0;
        #pragma unroll
        for (int i = 0; i < 4; i++) {
            Sv[i][0] = valid0 ? Sv[i][0] * 0.125f : -INFINITY;
            Sv[i][1] = valid1 ? Sv[i][1] * 0.125f : -INFINITY;
        }

        #pragma unroll
        for (int i = 0; i < 4; i++) {
            float tm = fmaxf(Sv[i][0], Sv[i][1]);
            #pragma unroll
            for (int off = 1; off < 16; off <<= 1)
                tm = fmaxf(tm, __shfl_xor_sync(0xffffffffu, tm, off));
            float mn = fmaxf(m[i], tm);
            float p0 = expf(Sv[i][0] - mn);
            float p1 = expf(Sv[i][1] - mn);
            float ts = p0 + p1;
            #pragma unroll
            for (int off = 1; off < 16; off <<= 1)
                ts += __shfl_xor_sync(0xffffffffu, ts, off);
            float corr = expf(m[i] - mn);
            l[i] = l[i] * corr + ts;
            m[i] = mn;
            #pragma unroll
            for (int j = 0; j < 4; j++) O[i][j] *= corr;
            Ps[ty*4 + i][tx*2 + 0] = p0;
            Ps[ty*4 + i][tx*2 + 1] = p1;
        }
        __syncthreads();

        #pragma unroll 4
        for (int c = 0; c < 32; c++) {
            float4 vv = *reinterpret_cast<const float4*>(&Vs[c][tx*4]);
            #pragma unroll
            for (int i = 0; i < 4; i++) {
                float pv = Ps[ty*4 + i][c];
                O[i][0] += pv * vv.x; O[i][1] += pv * vv.y;
                O[i][2] += pv * vv.z; O[i][3] += pv * vv.w;
            }
        }
    }
    __syncthreads();

    if (tid < 64) {
        float p = 1.f;
        #pragma unroll 8
        for (int d = 0; d < 64; d++) { p *= cosf(Qs[tid][d]); Qs[tid][d] = p; }
    }
    __syncthreads();

    const float w = 1.f / (1.f + expf(-qwp[0]));
    float* AOg = AO + ((size_t)(b * S_ + qt * 64)) * E_ + h * 64;
    #pragma unroll
    for (int i = 0; i < 4; i++) {
        int r = ty * 4 + i;
        float invl = 1.f / l[i];
        int d0 = tx * 4;
        float4 o;
        o.x = w * Qs[r][d0+0] + (1.f - w) * O[i][0] * invl;
        o.y = w * Qs[r][d0+1] + (1.f - w) * O[i][1] * invl;
        o.z = w * Qs[r][d0+2] + (1.f - w) * O[i][2] * invl;
        o.w = w * Qs[r][d0+3] + (1.f - w) * O[i][3] * invl;
        *reinterpret_cast<float4*>(AOg + (size_t)r * E_ + d0) = o;
    }
}

// ============================================================================
// out = LayerNorm(X + Y) * g + b
// ============================================================================
__global__ __launch_bounds__(256) void add_ln_kernel(
    const float* __restrict__ X, const float* __restrict__ Y,
    const float* __restrict__ g, const float* __restrict__ bt,
    float* __restrict__ out)
{
    const int row = blockIdx.x;
    const int tid = threadIdx.x;
    __shared__ float buf[1024];
    __shared__ float red[8];

    const float* Xr = X + (size_t)row * 1024;
    const float* Yr = Y + (size_t)row * 1024;

    float s = 0.f;
    #pragma unroll
    for (int i = 0; i < 4; i++) {
        int idx = tid + i * 256;
        float v = Xr[idx] + Yr[idx];
        buf[idx] = v;
        s += v;
    }
    #pragma unroll
    for (int off = 16; off; off >>= 1) s += __shfl_xor_sync(~0u, s, off);
    if ((tid & 31) == 0) red[tid >> 5] = s;
    __syncthreads();
    float tot = 0.f;
    #pragma unroll
    for (int i = 0; i < 8; i++) tot += red[i];
    const float mean = tot * (1.f / 1024.f);
    __syncthreads();

    float vs = 0.f;
    #pragma unroll
    for (int i = 0; i < 4; i++) {
        float d = buf[tid + i * 256] - mean;
        vs += d * d;
    }
    #pragma unroll
    for (int off = 16; off; off >>= 1) vs += __shfl_xor_sync(~0u, vs, off);
    if ((tid & 31) == 0) red[tid >> 5] = vs;
    __syncthreads();
    float vtot = 0.f;
    #pragma unroll
    for (int i = 0; i < 8; i++) vtot += red[i];
    const float rstd = rsqrtf(vtot * (1.f / 1024.f) + 1e-5f);

    #pragma unroll
    for (int i = 0; i < 4; i++) {
        int idx = tid + i * 256;
        out[(size_t)row * 1024 + idx] = (buf[idx] - mean) * rstd * g[idx] + bt[idx];
    }
}

// ============================================================================
// HM = wgt*cumprod(cos(X1_row)) + (1-wgt)*relu(H1)
// ============================================================================
__global__ __launch_bounds__(256) void ffn_mix_kernel(
    const float* __restrict__ X1, const float* __restrict__ H1,
    const float* __restrict__ qwp, float* __restrict__ HM)
{
    const int row = blockIdx.x;
    const int tid = threadIdx.x;
    __shared__ float seg[256];

    float4 xv = *reinterpret_cast<const float4*>(X1 + (size_t)row * 1024 + tid * 4);
    float c0 = cosf(xv.x), c1 = cosf(xv.y), c2 = cosf(xv.z), c3 = cosf(xv.w);
    float p = c0 * c1 * c2 * c3;
    seg[tid] = p;
    __syncthreads();
    #pragma unroll
    for (int off = 1; off < 256; off <<= 1) {
        float t = (tid >= off) ? seg[tid - off] : 1.f;
        __syncthreads();
        seg[tid] *= t;
        __syncthreads();
    }
    float pre = (tid > 0) ? seg[tid - 1] : 1.f;
    float q0 = pre * c0;
    float q1 = q0 * c1;
    float q2 = q1 * c2;
    float q3 = q2 * c3;

    const float w = 1.f / (1.f + expf(-qwp[0]));
    float4 hv = *reinterpret_cast<const float4*>(H1 + (size_t)row * 1024 + tid * 4);
    float4 o;
    o.x = w * q0 + (1.f - w) * fmaxf(hv.x, 0.f);
    o.y = w * q1 + (1.f - w) * fmaxf(hv.y, 0.f);
    o.z = w * q2 + (1.f - w) * fmaxf(hv.z, 0.f);
    o.w = w * q3 + (1.f - w) * fmaxf(hv.w, 0.f);
    *reinterpret_cast<float4*>(HM + (size_t)row * 1024 + tid * 4) = o;
}

// ============================================================================
// launch
// ============================================================================
extern "C" void kernel_launch(void* const* d_in, const int* in_sizes, int n_in,
                              void* d_out, int out_size)
{
    const float* x       = (const float*)d_in[0];
    const int*   mask    = (const int*)  d_in[1];
    const float* wq      = (const float*)d_in[2];
    const float* wk      = (const float*)d_in[3];
    const float* wv      = (const float*)d_in[4];
    const float* wo      = (const float*)d_in[5];
    const float* attn_qw = (const float*)d_in[7];
    const float* w1      = (const float*)d_in[8];
    const float* b1      = (const float*)d_in[9];
    const float* w2      = (const float*)d_in[10];
    const float* b2      = (const float*)d_in[11];
    const float* ffn_qw  = (const float*)d_in[13];
    const float* ln1g    = (const float*)d_in[14];
    const float* ln1b    = (const float*)d_in[15];
    const float* ln2g    = (const float*)d_in[16];
    const float* ln2b    = (const float*)d_in[17];
    float* out = (float*)d_out;

    float *Qp, *Kp, *Vp, *AOp, *X1p, *Tp, *HMp;
    cudaGetSymbolAddress((void**)&Qp,  g_Q);
    cudaGetSymbolAddress((void**)&Kp,  g_Kb);
    cudaGetSymbolAddress((void**)&Vp,  g_Vb);
    cudaGetSymbolAddress((void**)&AOp, g_AO);
    cudaGetSymbolAddress((void**)&X1p, g_X1);
    cudaGetSymbolAddress((void**)&Tp,  g_T);
    cudaGetSymbolAddress((void**)&HMp, g_HM);

    dim3 gg(E_ / 128, M_ / 128);   // (8, 32)

    // QKV projections
    gemm_tc_kernel<<<gg, 256>>>(x, wq, nullptr, Qp, M_, E_, E_);
    gemm_tc_kernel<<<gg, 256>>>(x, wk, nullptr, Kp, M_, E_, E_);
    gemm_tc_kernel<<<gg, 256>>>(x, wv, nullptr, Vp, M_, E_, E_);

    // attention + quantum mix
    attn_kernel<<<dim3(S_ / 64, B_ * H_), 256>>>(Qp, Kp, Vp, mask, attn_qw, AOp);

    // output projection, residual + LN1
    gemm_tc_kernel<<<gg, 256>>>(AOp, wo, nullptr, Tp, M_, E_, E_);
    add_ln_kernel<<<M_, 256>>>(x, Tp, ln1g, ln1b, X1p);

    // FFN
    gemm_tc_kernel<<<gg, 256>>>(X1p, w1, b1, Tp, M_, E_, E_);
    ffn_mix_kernel<<<M_, 256>>>(X1p, Tp, ffn_qw, HMp);
    gemm_tc_kernel<<<gg, 256>>>(HMp, w2, b2, Tp, M_, E_, E_);
    add_ln_kernel<<<M_, 256>>>(X1p, Tp, ln2g, ln2b, out);
}